// round 4
// baseline (speedup 1.0000x reference)
#include <cuda_runtime.h>
#include <math.h>

// ---------------------------------------------------------------------------
// FNO block: 4 x (truncated spectral conv + 1x1 conv + gelu)
// B=64, N=16384, C=32, MODES=16. All fp32, f32x2-packed FMA.
// ---------------------------------------------------------------------------
#define N_    16384
#define B_    64
#define C_    32
#define MODES 16
#define NSPLIT 8
#define PITCH 132

typedef unsigned long long u64;

// ------------------------------- scratch -----------------------------------
__device__ float g_buf[B_ * N_ * C_];            // 128 MiB ping buffer
__device__ float g_S[B_ * NSPLIT * MODES * C_ * 2];
__device__ float g_W[B_ * 62 * C_];
__device__ float g_bias[B_ * C_];
__device__ float g_twC[MODES * N_];              // cos(2 pi m n / N)
__device__ float g_twS[MODES * N_];              // sin(2 pi m n / N)

// ------------------------------ f32x2 helpers ------------------------------
__device__ __forceinline__ u64 f2fma(u64 a, u64 b, u64 c) {
    u64 d;
    asm("fma.rn.f32x2 %0,%1,%2,%3;" : "=l"(d) : "l"(a), "l"(b), "l"(c));
    return d;
}
__device__ __forceinline__ u64 f2mul(u64 a, u64 b) {
    u64 d;
    asm("mul.rn.f32x2 %0,%1,%2;" : "=l"(d) : "l"(a), "l"(b));
    return d;
}
__device__ __forceinline__ u64 f2add(u64 a, u64 b) {
    u64 d;
    asm("add.rn.f32x2 %0,%1,%2;" : "=l"(d) : "l"(a), "l"(b));
    return d;
}
__device__ __forceinline__ u64 pk2(float lo, float hi) {
    u64 d;
    asm("mov.b64 %0,{%1,%2};" : "=l"(d) : "f"(lo), "f"(hi));
    return d;
}
__device__ __forceinline__ float2 upk(u64 a) {
    float lo, hi;
    asm("mov.b64 {%0,%1},%2;" : "=f"(lo), "=f"(hi) : "l"(a));
    return make_float2(lo, hi);
}

__device__ __forceinline__ float gelu_f(float h) {
    // 0.5 h (1+tanh(z)) == h * sigmoid(2z),  2z = 1.59576912 h + 0.07135482 h^3
    float u = h * h;
    float y = h * fmaf(u, 0.0713548163f, 1.5957691216f);
    return __fdividef(h, 1.0f + __expf(-y));
}

// ------------------------------- init --------------------------------------
__global__ void k_init() {
    int idx = blockIdx.x * 256 + threadIdx.x;      // 0 .. 16*16384-1
    int m = idx >> 14;
    int n = idx & (N_ - 1);
    int r = (m * n) & (N_ - 1);
    float s, c;
    sincospif((float)r * (1.0f / 8192.0f), &s, &c);  // exact phase: pi*r/8192
    g_twC[idx] = c;
    g_twS[idx] = s;
}

// ----------------------- K1: partial forward DFT ---------------------------
// grid (NSPLIT, B), 256 threads. Warp w handles 256 consecutive n.
// lane: cg = l&3 (channels 8cg..8cg+7 -> 4 channel-pairs), pg = l>>2
// owns modes m0=2pg, m1=2pg+1 (4 parts: cos m0, sin m0, cos m1, sin m1).
// Twiddles generated by in-register rotation (no loads in the chain).
__global__ void __launch_bounds__(256) k_dft(const float* __restrict__ xext, int d) {
    const float* x = (d == 0) ? xext : g_buf;
    int sp = blockIdx.x, b = blockIdx.y;
    int t = threadIdx.x, w = t >> 5, l = t & 31;
    int cg = l & 3, pg = l >> 2;
    int m0 = 2 * pg, m1 = 2 * pg + 1;
    const float4* x4 = (const float4*)(x + ((size_t)b << 19));
    int n0 = sp * 2048 + w * 256;

    // init twiddles at n0 and per-step rotation constants
    float c0f, s0f, c1f, s1f, C0f, S0f, C1f, S1f;
    {
        int r0 = (m0 * n0) & (N_ - 1);
        int r1 = (m1 * n0) & (N_ - 1);
        sincospif((float)r0 * (1.0f / 8192.0f), &s0f, &c0f);
        sincospif((float)r1 * (1.0f / 8192.0f), &s1f, &c1f);
        sincospif((float)m0 * (1.0f / 8192.0f), &S0f, &C0f);
        sincospif((float)m1 * (1.0f / 8192.0f), &S1f, &C1f);
    }
    u64 tc0 = pk2(c0f, c0f), ts0 = pk2(s0f, s0f);
    u64 tc1 = pk2(c1f, c1f), ts1 = pk2(s1f, s1f);
    u64 SC0 = pk2(C0f, C0f), SS0 = pk2(S0f, S0f), nSS0 = pk2(-S0f, -S0f);
    u64 SC1 = pk2(C1f, C1f), SS1 = pk2(S1f, S1f), nSS1 = pk2(-S1f, -S1f);

    u64 acc[4][4];
#pragma unroll
    for (int i = 0; i < 4; i++)
#pragma unroll
        for (int j = 0; j < 4; j++) acc[i][j] = 0ull;

#pragma unroll 2
    for (int nn = 0; nn < 256; nn++) {
        int n = n0 + nn;
        float4 v0 = __ldg(&x4[(size_t)n * 8 + 2 * cg]);
        float4 v1 = __ldg(&x4[(size_t)n * 8 + 2 * cg + 1]);
        u64 xp[4];
        xp[0] = pk2(v0.x, v0.y);
        xp[1] = pk2(v0.z, v0.w);
        xp[2] = pk2(v1.x, v1.y);
        xp[3] = pk2(v1.z, v1.w);
#pragma unroll
        for (int j = 0; j < 4; j++) {
            acc[0][j] = f2fma(xp[j], tc0, acc[0][j]);
            acc[1][j] = f2fma(xp[j], ts0, acc[1][j]);
            acc[2][j] = f2fma(xp[j], tc1, acc[2][j]);
            acc[3][j] = f2fma(xp[j], ts1, acc[3][j]);
        }
        // rotate twiddles: c' = c*C - s*S ; s' = s*C + c*S
        u64 nc0 = f2fma(ts0, nSS0, f2mul(tc0, SC0));
        u64 ns0 = f2fma(tc0, SS0, f2mul(ts0, SC0));
        u64 nc1 = f2fma(ts1, nSS1, f2mul(tc1, SC1));
        u64 ns1 = f2fma(tc1, SS1, f2mul(ts1, SC1));
        tc0 = nc0; ts0 = ns0; tc1 = nc1; ts1 = ns1;
    }

    // block reduction over the 8 warps (fixed order -> deterministic)
    __shared__ u64 red[8][512];
#pragma unroll
    for (int i = 0; i < 4; i++)
#pragma unroll
        for (int j = 0; j < 4; j++) red[w][l * 16 + i * 4 + j] = acc[i][j];
    __syncthreads();

    for (int s = t; s < 512; s += 256) {
        u64 a = red[0][s];
#pragma unroll
        for (int w2 = 1; w2 < 8; w2++) a = f2add(a, red[w2][s]);
        int lane = s >> 4, k = s & 15, i = k >> 2, j = k & 3;
        int q  = 4 * (lane >> 2) + i;
        int cp = 4 * (lane & 3) + j;
        int m = q >> 1, reim = q & 1;
        float2 f = upk(a);
        float sg = reim ? -1.0f : 1.0f;   // Im(X) = -sum x*sin
        size_t base = ((((size_t)b * NSPLIT + sp) * MODES + m) * C_ + 2 * cp);
        g_S[base * 2 + reim]       = sg * f.x;
        g_S[(base + 1) * 2 + reim] = sg * f.y;
    }
}

// --------------------- K2: mix + fused weight build ------------------------
__global__ void __launch_bounds__(512) k_mix(const float* __restrict__ Wr,
                                             const float* __restrict__ Wi,
                                             const float* __restrict__ ck,
                                             const float* __restrict__ cb, int d) {
    int b = blockIdx.x, t = threadIdx.x;
    int m = t >> 5, o = t & 31;
    __shared__ float xr[MODES][C_], xi[MODES][C_];
    {
        const float2* S2 = (const float2*)g_S;
        float re = 0.f, im = 0.f;
#pragma unroll
        for (int s = 0; s < NSPLIT; s++) {
            float2 v = S2[(((size_t)b * NSPLIT + s) * MODES + m) * C_ + o];
            re += v.x;
            im += v.y;
        }
        xr[m][o] = re;
        xi[m][o] = im;
    }
    __syncthreads();

    float oR = 0.f, oI = 0.f;
    const float* wr = Wr + (size_t)d * C_ * C_ * MODES;
    const float* wi = Wi + (size_t)d * C_ * C_ * MODES;
#pragma unroll 4
    for (int i = 0; i < C_; i++) {
        float a  = xr[m][i];
        float bi = xi[m][i];
        float r_ = wr[(i * C_ + o) * MODES + m];
        float q_ = wi[(i * C_ + o) * MODES + m];
        oR += a * r_ - bi * q_;
        oI += a * q_ + bi * r_;
    }
    float* Wb = g_W + (size_t)b * 62 * C_;
    if (m >= 1) {
        Wb[(m - 1) * C_ + o]  = oR * (2.0f / (float)N_);
        Wb[(14 + m) * C_ + o] = -oI * (2.0f / (float)N_);
    } else {
        g_bias[b * C_ + o] = oR * (1.0f / (float)N_) + cb[d * C_ + o];
    }
    for (int lin = t; lin < 1024; lin += 512) {
        int i = lin >> 5, oo = lin & 31;
        Wb[(30 + i) * C_ + oo] = ck[((size_t)d * C_ + i) * C_ + oo];
    }
}

// -------------- K3: fused inverse-eval + 1x1 conv + gelu -------------------
// grid (N/128, B), 128 threads. out[b,n,o] = gelu(A[n,:62] @ Wf[:,o] + bias)
// f32x2 packed over OUTPUT-channel pairs; W rows read raw (no duplication).
// warp w: nh = w&1 (64-n half), og = w>>1 (16-output half).
// lane: 2 n (nl = 64*nh + 2*l), 16 outputs -> acc[2][8] u64.
__global__ void __launch_bounds__(128) k_out(const float* __restrict__ xext,
                                             float* __restrict__ oext, int d) {
    const float* xin = (d == 0) ? xext : g_buf;
    float* out       = (d == 3) ? oext : g_buf;
    int tile = blockIdx.x, b = blockIdx.y;
    int t = threadIdx.x;
    int n0 = tile << 7;

    __shared__ float As[62 * PITCH];                 // 32736 B
    __shared__ __align__(16) u64 Wu[62 * 16];        // 7936 B (raw W rows)
    __shared__ float bs[C_];

    // trig rows 0..29
#pragma unroll
    for (int r = 0; r < 15; r++) As[r * PITCH + t] = g_twC[(r + 1) * N_ + n0 + t];
#pragma unroll
    for (int r = 15; r < 30; r++) As[r * PITCH + t] = g_twS[(r - 14) * N_ + n0 + t];
    // x rows 30..61 (transposed)
    const float4* x4 = (const float4*)(xin + ((size_t)b << 19));
#pragma unroll
    for (int k = 0; k < 8; k++) {
        int lin = k * 128 + t;
        int cq = lin & 7, nl = lin >> 3;
        float4 v = x4[(size_t)(n0 + nl) * 8 + cq];
        As[(30 + 4 * cq) * PITCH + nl] = v.x;
        As[(31 + 4 * cq) * PITCH + nl] = v.y;
        As[(32 + 4 * cq) * PITCH + nl] = v.z;
        As[(33 + 4 * cq) * PITCH + nl] = v.w;
    }
    const u64* Wb8 = (const u64*)(g_W + (size_t)b * 62 * C_);
    for (int lin = t; lin < 62 * 16; lin += 128) Wu[lin] = Wb8[lin];
    if (t < 32) bs[t] = g_bias[b * C_ + t];
    __syncthreads();

    int w = t >> 5, l = t & 31;
    int nh = w & 1, og = w >> 1;
    int nl = 64 * nh + 2 * l;
    int o0 = og * 16;

    u64 acc[2][8];
#pragma unroll
    for (int i = 0; i < 2; i++)
#pragma unroll
        for (int k = 0; k < 8; k++) acc[i][k] = 0ull;

    const float* ap = As + nl;
    const u64* wp = Wu + og * 8;
#pragma unroll 2
    for (int r = 0; r < 62; r++) {
        float2 a2 = *(const float2*)(ap + r * PITCH);
        u64 a0 = pk2(a2.x, a2.x);
        u64 a1 = pk2(a2.y, a2.y);
        ulonglong2 w0 = *(const ulonglong2*)(wp + r * 16);
        ulonglong2 w1 = *(const ulonglong2*)(wp + r * 16 + 2);
        ulonglong2 w2 = *(const ulonglong2*)(wp + r * 16 + 4);
        ulonglong2 w3 = *(const ulonglong2*)(wp + r * 16 + 6);
        u64 ws[8] = {w0.x, w0.y, w1.x, w1.y, w2.x, w2.y, w3.x, w3.y};
#pragma unroll
        for (int k = 0; k < 8; k++) {
            acc[0][k] = f2fma(a0, ws[k], acc[0][k]);
            acc[1][k] = f2fma(a1, ws[k], acc[1][k]);
        }
    }

    // epilogue: bias + gelu + store (each thread: 2 n x 16 channels)
#pragma unroll
    for (int nn = 0; nn < 2; nn++) {
        float res[16];
#pragma unroll
        for (int k = 0; k < 8; k++) {
            float2 f = upk(acc[nn][k]);
            res[2 * k]     = gelu_f(f.x + bs[o0 + 2 * k]);
            res[2 * k + 1] = gelu_f(f.y + bs[o0 + 2 * k + 1]);
        }
        float* op = out + (((size_t)b << 14) + n0 + nl + nn) * C_ + o0;
#pragma unroll
        for (int j = 0; j < 4; j++)
            *(float4*)(op + 4 * j) =
                make_float4(res[4 * j], res[4 * j + 1], res[4 * j + 2], res[4 * j + 3]);
    }
}

// ------------------------------- launch ------------------------------------
extern "C" void kernel_launch(void* const* d_in, const int* in_sizes, int n_in,
                              void* d_out, int out_size) {
    const float* x  = (const float*)d_in[0];
    const float* Wr = (const float*)d_in[1];
    const float* Wi = (const float*)d_in[2];
    const float* ck = (const float*)d_in[3];
    const float* cb = (const float*)d_in[4];
    float* out = (float*)d_out;

    k_init<<<(MODES * N_) / 256, 256>>>();
    for (int d = 0; d < 4; d++) {
        k_dft<<<dim3(NSPLIT, B_), 256>>>(x, d);
        k_mix<<<B_, 512>>>(Wr, Wi, ck, cb, d);
        k_out<<<dim3(N_ / 128, B_), 128>>>(x, out, d);
    }
}

// round 8
// speedup vs baseline: 1.3562x; 1.3562x over previous
#include <cuda_runtime.h>
#include <math.h>

// ---------------------------------------------------------------------------
// FNO block: 4 x (truncated spectral conv + 1x1 conv + gelu)
// B=64, N=16384, C=32, MODES=16. All fp32, f32x2-packed FMA.
// ---------------------------------------------------------------------------
#define N_    16384
#define B_    64
#define C_    32
#define MODES 16
#define NSPLIT 8
#define PITCH 132

typedef unsigned long long u64;

// ------------------------------- scratch -----------------------------------
__device__ float g_buf[B_ * N_ * C_];            // 128 MiB ping buffer
__device__ float g_S[B_ * NSPLIT * MODES * C_ * 2];
__device__ float g_W[B_ * 62 * C_];
__device__ float g_bias[B_ * C_];
__device__ float g_twC[MODES * N_];              // cos(2 pi m n / N)
__device__ float g_twS[MODES * N_];              // sin(2 pi m n / N)
__device__ __align__(16) float g_twF[N_ * 32];   // [n][q]: q=2m+ri, m=0..15

// ------------------------------ f32x2 helpers ------------------------------
__device__ __forceinline__ u64 f2fma(u64 a, u64 b, u64 c) {
    u64 d;
    asm("fma.rn.f32x2 %0,%1,%2,%3;" : "=l"(d) : "l"(a), "l"(b), "l"(c));
    return d;
}
__device__ __forceinline__ u64 f2add(u64 a, u64 b) {
    u64 d;
    asm("add.rn.f32x2 %0,%1,%2;" : "=l"(d) : "l"(a), "l"(b));
    return d;
}
__device__ __forceinline__ u64 pk2(float lo, float hi) {
    u64 d;
    asm("mov.b64 %0,{%1,%2};" : "=l"(d) : "f"(lo), "f"(hi));
    return d;
}
__device__ __forceinline__ float2 upk(u64 a) {
    float lo, hi;
    asm("mov.b64 {%0,%1},%2;" : "=f"(lo), "=f"(hi) : "l"(a));
    return make_float2(lo, hi);
}

__device__ __forceinline__ float gelu_f(float h) {
    // 0.5*h*(1 + tanh(0.79788456*(h + 0.044715 h^3)))
    float u = h * h;
    float z = h * fmaf(u, 0.0356774081f, 0.7978845608f);
    float th;
    asm("tanh.approx.f32 %0,%1;" : "=f"(th) : "f"(z));
    float hh = 0.5f * h;
    return fmaf(hh, th, hh);
}

// ------------------------------- init --------------------------------------
__global__ void k_init() {
    int idx = blockIdx.x * 256 + threadIdx.x;      // 0 .. 16*16384-1
    int m = idx >> 14;
    int n = idx & (N_ - 1);
    int r = (m * n) & (N_ - 1);
    float s, c;
    sincospif((float)r * (1.0f / 8192.0f), &s, &c);  // exact phase: pi*r/8192
    g_twC[idx] = c;
    g_twS[idx] = s;
    g_twF[n * 32 + 2 * m]     = c;
    g_twF[n * 32 + 2 * m + 1] = s;
}

// ----------------------- K1: partial forward DFT ---------------------------
// grid (NSPLIT, B), 256 threads. Warp w handles 256 consecutive n.
// lane: cg = l&3 (channels 8cg..8cg+7 -> 4 channel-pairs), pg = l>>2
// (parts 4pg..4pg+3 where part q = 2m+reim). tw via one LDG.128 per n.
__global__ void __launch_bounds__(256) k_dft(const float* __restrict__ xext, int d) {
    const float* x = (d == 0) ? xext : g_buf;
    int sp = blockIdx.x, b = blockIdx.y;
    int t = threadIdx.x, w = t >> 5, l = t & 31;
    int cg = l & 3, pg = l >> 2;
    const float4* x4 = (const float4*)(x + ((size_t)b << 19));
    const float4* tw8 = (const float4*)g_twF;     // [n][8 groups of 4]
    int n0 = sp * 2048 + w * 256;

    u64 acc[4][4];
#pragma unroll
    for (int i = 0; i < 4; i++)
#pragma unroll
        for (int j = 0; j < 4; j++) acc[i][j] = 0ull;

#pragma unroll 4
    for (int nn = 0; nn < 256; nn++) {
        int n = n0 + nn;
        float4 v0 = __ldg(&x4[(size_t)n * 8 + 2 * cg]);
        float4 v1 = __ldg(&x4[(size_t)n * 8 + 2 * cg + 1]);
        float4 tf = __ldg(&tw8[(size_t)n * 8 + pg]);
        u64 xp[4];
        xp[0] = pk2(v0.x, v0.y);
        xp[1] = pk2(v0.z, v0.w);
        xp[2] = pk2(v1.x, v1.y);
        xp[3] = pk2(v1.z, v1.w);
        u64 tq[4];
        tq[0] = pk2(tf.x, tf.x);
        tq[1] = pk2(tf.y, tf.y);
        tq[2] = pk2(tf.z, tf.z);
        tq[3] = pk2(tf.w, tf.w);
#pragma unroll
        for (int i = 0; i < 4; i++)
#pragma unroll
            for (int j = 0; j < 4; j++) acc[i][j] = f2fma(xp[j], tq[i], acc[i][j]);
    }

    // block reduction over the 8 warps (fixed order -> deterministic)
    __shared__ u64 red[8][512];
#pragma unroll
    for (int i = 0; i < 4; i++)
#pragma unroll
        for (int j = 0; j < 4; j++) red[w][l * 16 + i * 4 + j] = acc[i][j];
    __syncthreads();

    for (int s = t; s < 512; s += 256) {
        u64 a = red[0][s];
#pragma unroll
        for (int w2 = 1; w2 < 8; w2++) a = f2add(a, red[w2][s]);
        int lane = s >> 4, k = s & 15, i = k >> 2, j = k & 3;
        int q  = 4 * (lane >> 2) + i;
        int cp = 4 * (lane & 3) + j;
        int m = q >> 1, reim = q & 1;
        float2 f = upk(a);
        float sg = reim ? -1.0f : 1.0f;   // Im(X) = -sum x*sin
        size_t base = ((((size_t)b * NSPLIT + sp) * MODES + m) * C_ + 2 * cp);
        g_S[base * 2 + reim]       = sg * f.x;
        g_S[(base + 1) * 2 + reim] = sg * f.y;
    }
}

// --------------------- K2: mix + fused weight build ------------------------
__global__ void __launch_bounds__(512) k_mix(const float* __restrict__ Wr,
                                             const float* __restrict__ Wi,
                                             const float* __restrict__ ck,
                                             const float* __restrict__ cb, int d) {
    int b = blockIdx.x, t = threadIdx.x;
    int m = t >> 5, o = t & 31;
    __shared__ float xr[MODES][C_], xi[MODES][C_];
    {
        const float2* S2 = (const float2*)g_S;
        float re = 0.f, im = 0.f;
#pragma unroll
        for (int s = 0; s < NSPLIT; s++) {
            float2 v = S2[(((size_t)b * NSPLIT + s) * MODES + m) * C_ + o];
            re += v.x;
            im += v.y;
        }
        xr[m][o] = re;
        xi[m][o] = im;
    }
    __syncthreads();

    float oR = 0.f, oI = 0.f;
    const float* wr = Wr + (size_t)d * C_ * C_ * MODES;
    const float* wi = Wi + (size_t)d * C_ * C_ * MODES;
#pragma unroll 4
    for (int i = 0; i < C_; i++) {
        float a  = xr[m][i];
        float bi = xi[m][i];
        float r_ = wr[(i * C_ + o) * MODES + m];
        float q_ = wi[(i * C_ + o) * MODES + m];
        oR += a * r_ - bi * q_;
        oI += a * q_ + bi * r_;
    }
    float* Wb = g_W + (size_t)b * 62 * C_;
    if (m >= 1) {
        Wb[(m - 1) * C_ + o]  = oR * (2.0f / (float)N_);
        Wb[(14 + m) * C_ + o] = -oI * (2.0f / (float)N_);
    } else {
        g_bias[b * C_ + o] = oR * (1.0f / (float)N_) + cb[d * C_ + o];
    }
    for (int lin = t; lin < 1024; lin += 512) {
        int i = lin >> 5, oo = lin & 31;
        Wb[(30 + i) * C_ + oo] = ck[((size_t)d * C_ + i) * C_ + oo];
    }
}

// -------------- K3: fused inverse-eval + 1x1 conv + gelu -------------------
// grid (N/128, B), 128 threads. out[b,n,o] = gelu(A[n,:62] @ Wf[:,o] + bias)
// f32x2 packed over OUTPUT-channel pairs; software-pipelined r-loop.
__global__ void __launch_bounds__(128, 5) k_out(const float* __restrict__ xext,
                                                float* __restrict__ oext, int d) {
    const float* xin = (d == 0) ? xext : g_buf;
    float* out       = (d == 3) ? oext : g_buf;
    int tile = blockIdx.x, b = blockIdx.y;
    int t = threadIdx.x;
    int n0 = tile << 7;

    __shared__ float As[62 * PITCH];                 // 32736 B
    __shared__ __align__(16) u64 Wu[62 * 16];        // 7936 B (raw W rows)
    __shared__ float bs[C_];

    // trig rows 0..29
#pragma unroll
    for (int r = 0; r < 15; r++) As[r * PITCH + t] = g_twC[(r + 1) * N_ + n0 + t];
#pragma unroll
    for (int r = 15; r < 30; r++) As[r * PITCH + t] = g_twS[(r - 14) * N_ + n0 + t];
    // x rows 30..61 (transposed)
    const float4* x4 = (const float4*)(xin + ((size_t)b << 19));
#pragma unroll
    for (int k = 0; k < 8; k++) {
        int lin = k * 128 + t;
        int cq = lin & 7, nl = lin >> 3;
        float4 v = x4[(size_t)(n0 + nl) * 8 + cq];
        As[(30 + 4 * cq) * PITCH + nl] = v.x;
        As[(31 + 4 * cq) * PITCH + nl] = v.y;
        As[(32 + 4 * cq) * PITCH + nl] = v.z;
        As[(33 + 4 * cq) * PITCH + nl] = v.w;
    }
    const u64* Wb8 = (const u64*)(g_W + (size_t)b * 62 * C_);
    for (int lin = t; lin < 62 * 16; lin += 128) Wu[lin] = Wb8[lin];
    if (t < 32) bs[t] = g_bias[b * C_ + t];
    __syncthreads();

    int w = t >> 5, l = t & 31;
    int nh = w & 1, og = w >> 1;
    int nl = 64 * nh + 2 * l;
    int o0 = og * 16;

    u64 acc[2][8];
#pragma unroll
    for (int i = 0; i < 2; i++)
#pragma unroll
        for (int k = 0; k < 8; k++) acc[i][k] = 0ull;

    const float* ap = As + nl;
    const ulonglong2* wpv = (const ulonglong2*)Wu + og * 4;   // per r: +8

    // software pipeline: prefetch r+1 while FMA-ing r (clamped at the tail)
    float2 a2 = *(const float2*)(ap);
    ulonglong2 w0 = wpv[0], w1 = wpv[1], w2 = wpv[2], w3 = wpv[3];
#pragma unroll 2
    for (int r = 0; r < 62; r++) {
        int rn = (r < 61) ? (r + 1) : 61;
        float2 a2n = *(const float2*)(ap + rn * PITCH);
        const ulonglong2* wn = wpv + rn * 8;
        ulonglong2 n0v = wn[0], n1v = wn[1], n2v = wn[2], n3v = wn[3];

        u64 a0 = pk2(a2.x, a2.x);
        u64 a1 = pk2(a2.y, a2.y);
        acc[0][0] = f2fma(a0, w0.x, acc[0][0]);
        acc[1][0] = f2fma(a1, w0.x, acc[1][0]);
        acc[0][1] = f2fma(a0, w0.y, acc[0][1]);
        acc[1][1] = f2fma(a1, w0.y, acc[1][1]);
        acc[0][2] = f2fma(a0, w1.x, acc[0][2]);
        acc[1][2] = f2fma(a1, w1.x, acc[1][2]);
        acc[0][3] = f2fma(a0, w1.y, acc[0][3]);
        acc[1][3] = f2fma(a1, w1.y, acc[1][3]);
        acc[0][4] = f2fma(a0, w2.x, acc[0][4]);
        acc[1][4] = f2fma(a1, w2.x, acc[1][4]);
        acc[0][5] = f2fma(a0, w2.y, acc[0][5]);
        acc[1][5] = f2fma(a1, w2.y, acc[1][5]);
        acc[0][6] = f2fma(a0, w3.x, acc[0][6]);
        acc[1][6] = f2fma(a1, w3.x, acc[1][6]);
        acc[0][7] = f2fma(a0, w3.y, acc[0][7]);
        acc[1][7] = f2fma(a1, w3.y, acc[1][7]);
        a2 = a2n;
        w0 = n0v; w1 = n1v; w2 = n2v; w3 = n3v;
    }

    // epilogue: bias + gelu + store (each thread: 2 n x 16 channels)
#pragma unroll
    for (int nn = 0; nn < 2; nn++) {
        float res[16];
#pragma unroll
        for (int k = 0; k < 8; k++) {
            float2 f = upk(acc[nn][k]);
            res[2 * k]     = gelu_f(f.x + bs[o0 + 2 * k]);
            res[2 * k + 1] = gelu_f(f.y + bs[o0 + 2 * k + 1]);
        }
        float* op = out + (((size_t)b << 14) + n0 + nl + nn) * C_ + o0;
#pragma unroll
        for (int j = 0; j < 4; j++)
            *(float4*)(op + 4 * j) =
                make_float4(res[4 * j], res[4 * j + 1], res[4 * j + 2], res[4 * j + 3]);
    }
}

// ------------------------------- launch ------------------------------------
extern "C" void kernel_launch(void* const* d_in, const int* in_sizes, int n_in,
                              void* d_out, int out_size) {
    const float* x  = (const float*)d_in[0];
    const float* Wr = (const float*)d_in[1];
    const float* Wi = (const float*)d_in[2];
    const float* ck = (const float*)d_in[3];
    const float* cb = (const float*)d_in[4];
    float* out = (float*)d_out;

    k_init<<<(MODES * N_) / 256, 256>>>();
    for (int d = 0; d < 4; d++) {
        k_dft<<<dim3(NSPLIT, B_), 256>>>(x, d);
        k_mix<<<B_, 512>>>(Wr, Wi, ck, cb, d);
        k_out<<<dim3(N_ / 128, B_), 128>>>(x, out, d);
    }
}

// round 11
// speedup vs baseline: 1.6562x; 1.2212x over previous
#include <cuda_runtime.h>
#include <math.h>

// ---------------------------------------------------------------------------
// FNO block: 4 x (truncated spectral conv + 1x1 conv + gelu)
// B=64, N=16384, C=32, MODES=16. All fp32, f32x2-packed FMA.
// ---------------------------------------------------------------------------
#define N_    16384
#define B_    64
#define C_    32
#define MODES 16
#define NSPLIT 8
#define PITCH2 260

typedef unsigned long long u64;

// ------------------------------- scratch -----------------------------------
__device__ float g_buf[B_ * N_ * C_];            // 128 MiB ping buffer
__device__ float g_S[B_ * NSPLIT * MODES * C_ * 2];
__device__ float g_W[B_ * 62 * C_];
__device__ float g_bias[B_ * C_];
__device__ float g_twC[MODES * N_];              // cos(2 pi m n / N)
__device__ float g_twS[MODES * N_];              // sin(2 pi m n / N)
__device__ __align__(16) float g_twF[N_ * 32];   // [n][q]: q=2m+ri, m=0..15

// dynamic smem bytes for k_out: As 62*260 floats + Wu 62*16 u64 + bs 32 floats
#define KOUT_SMEM (62 * PITCH2 * 4 + 62 * 16 * 8 + 128)

// ------------------------------ f32x2 helpers ------------------------------
__device__ __forceinline__ u64 f2fma(u64 a, u64 b, u64 c) {
    u64 d;
    asm("fma.rn.f32x2 %0,%1,%2,%3;" : "=l"(d) : "l"(a), "l"(b), "l"(c));
    return d;
}
__device__ __forceinline__ u64 f2add(u64 a, u64 b) {
    u64 d;
    asm("add.rn.f32x2 %0,%1,%2;" : "=l"(d) : "l"(a), "l"(b));
    return d;
}
__device__ __forceinline__ u64 pk2(float lo, float hi) {
    u64 d;
    asm("mov.b64 %0,{%1,%2};" : "=l"(d) : "f"(lo), "f"(hi));
    return d;
}
__device__ __forceinline__ float2 upk(u64 a) {
    float lo, hi;
    asm("mov.b64 {%0,%1},%2;" : "=f"(lo), "=f"(hi) : "l"(a));
    return make_float2(lo, hi);
}

__device__ __forceinline__ float gelu_f(float h) {
    // 0.5*h*(1 + tanh(0.79788456*(h + 0.044715 h^3)))
    float u = h * h;
    float z = h * fmaf(u, 0.0356774081f, 0.7978845608f);
    float th;
    asm("tanh.approx.f32 %0,%1;" : "=f"(th) : "f"(z));
    float hh = 0.5f * h;
    return fmaf(hh, th, hh);
}

// ------------------------------- init --------------------------------------
__global__ void k_init() {
    int idx = blockIdx.x * 256 + threadIdx.x;      // 0 .. 16*16384-1
    int m = idx >> 14;
    int n = idx & (N_ - 1);
    int r = (m * n) & (N_ - 1);
    float s, c;
    sincospif((float)r * (1.0f / 8192.0f), &s, &c);  // exact phase: pi*r/8192
    g_twC[idx] = c;
    g_twS[idx] = s;
    g_twF[n * 32 + 2 * m]     = c;
    g_twF[n * 32 + 2 * m + 1] = s;
}

// ----------------------- K1: partial forward DFT ---------------------------
// grid (NSPLIT, B), 256 threads (8 warps). Warp w: 256 consecutive n,
// processed 2 per step (lane-halves by n-parity).
// lane (l<16 mirrored at l>=16 with other n): cg = l&3 -> channels 8cg..8cg+7
// (4 ch-pairs), pg = (l>>2)&3 -> parts q = 8pg..8pg+7 (q = 2m+reim).
// Per step per lane: 2 x LDG.128 + 2 tw LDG.128 -> 32 FFMA2.
__global__ void __launch_bounds__(256, 2) k_dft(const float* __restrict__ xext, int d) {
    const float* x = (d == 0) ? xext : g_buf;
    int sp = blockIdx.x, b = blockIdx.y;
    int t = threadIdx.x, w = t >> 5, l = t & 31;
    int nsel = l >> 4, cg = l & 3, pg = (l >> 2) & 3;
    const float4* x4 = (const float4*)(x + ((size_t)b << 19));
    const float4* tw8 = (const float4*)g_twF;     // [n][8 groups of 4]
    int n0 = sp * 2048 + w * 256;

    u64 acc[8][4];
#pragma unroll
    for (int i = 0; i < 8; i++)
#pragma unroll
        for (int j = 0; j < 4; j++) acc[i][j] = 0ull;

#pragma unroll 2
    for (int s = 0; s < 128; s++) {
        int n = n0 + 2 * s + nsel;
        float4 v0 = __ldg(&x4[(size_t)n * 8 + 2 * cg]);
        float4 v1 = __ldg(&x4[(size_t)n * 8 + 2 * cg + 1]);
        float4 ta = __ldg(&tw8[(size_t)n * 8 + 2 * pg]);
        float4 tb = __ldg(&tw8[(size_t)n * 8 + 2 * pg + 1]);
        u64 xp[4];
        xp[0] = pk2(v0.x, v0.y);
        xp[1] = pk2(v0.z, v0.w);
        xp[2] = pk2(v1.x, v1.y);
        xp[3] = pk2(v1.z, v1.w);
        float tf[8] = {ta.x, ta.y, ta.z, ta.w, tb.x, tb.y, tb.z, tb.w};
#pragma unroll
        for (int i = 0; i < 8; i++) {
            u64 tq = pk2(tf[i], tf[i]);
#pragma unroll
            for (int j = 0; j < 4; j++) acc[i][j] = f2fma(xp[j], tq, acc[i][j]);
        }
    }

    // merge the two n-parity lane-halves (lane l += lane l+16)
#pragma unroll
    for (int i = 0; i < 8; i++)
#pragma unroll
        for (int j = 0; j < 4; j++) {
            u64 o = __shfl_down_sync(0xffffffffu, acc[i][j], 16);
            acc[i][j] = f2add(acc[i][j], o);
        }

    // block reduction over the 8 warps (fixed order -> deterministic)
    __shared__ u64 red[8][16 * 32];
    if (l < 16) {
#pragma unroll
        for (int i = 0; i < 8; i++)
#pragma unroll
            for (int j = 0; j < 4; j++) red[w][l * 32 + i * 4 + j] = acc[i][j];
    }
    __syncthreads();

    for (int s = t; s < 512; s += 256) {
        u64 a = red[0][s];
#pragma unroll
        for (int w2 = 1; w2 < 8; w2++) a = f2add(a, red[w2][s]);
        int lane = s >> 5, k = s & 31;
        int cg2 = lane & 3, pg2 = lane >> 2;
        int i = k >> 2, j = k & 3;
        int q  = 8 * pg2 + i;
        int cp = 4 * cg2 + j;
        int m = q >> 1, reim = q & 1;
        float2 f = upk(a);
        float sg = reim ? -1.0f : 1.0f;   // Im(X) = -sum x*sin
        size_t base = ((((size_t)b * NSPLIT + sp) * MODES + m) * C_ + 2 * cp);
        g_S[base * 2 + reim]       = sg * f.x;
        g_S[(base + 1) * 2 + reim] = sg * f.y;
    }
}

// --------------------- K2: mix + fused weight build ------------------------
__global__ void __launch_bounds__(512) k_mix(const float* __restrict__ Wr,
                                             const float* __restrict__ Wi,
                                             const float* __restrict__ ck,
                                             const float* __restrict__ cb, int d) {
    int b = blockIdx.x, t = threadIdx.x;
    int m = t >> 5, o = t & 31;
    __shared__ float xr[MODES][C_], xi[MODES][C_];
    {
        const float2* S2 = (const float2*)g_S;
        float re = 0.f, im = 0.f;
#pragma unroll
        for (int s = 0; s < NSPLIT; s++) {
            float2 v = S2[(((size_t)b * NSPLIT + s) * MODES + m) * C_ + o];
            re += v.x;
            im += v.y;
        }
        xr[m][o] = re;
        xi[m][o] = im;
    }
    __syncthreads();

    float oR = 0.f, oI = 0.f;
    const float* wr = Wr + (size_t)d * C_ * C_ * MODES;
    const float* wi = Wi + (size_t)d * C_ * C_ * MODES;
#pragma unroll 4
    for (int i = 0; i < C_; i++) {
        float a  = xr[m][i];
        float bi = xi[m][i];
        float r_ = wr[(i * C_ + o) * MODES + m];
        float q_ = wi[(i * C_ + o) * MODES + m];
        oR += a * r_ - bi * q_;
        oI += a * q_ + bi * r_;
    }
    float* Wb = g_W + (size_t)b * 62 * C_;
    if (m >= 1) {
        Wb[(m - 1) * C_ + o]  = oR * (2.0f / (float)N_);
        Wb[(14 + m) * C_ + o] = -oI * (2.0f / (float)N_);
    } else {
        g_bias[b * C_ + o] = oR * (1.0f / (float)N_) + cb[d * C_ + o];
    }
    for (int lin = t; lin < 1024; lin += 512) {
        int i = lin >> 5, oo = lin & 31;
        Wb[(30 + i) * C_ + oo] = ck[((size_t)d * C_ + i) * C_ + oo];
    }
}

// -------------- K3: fused inverse-eval + 1x1 conv + gelu -------------------
// grid (N/256, B), 128 threads, dynamic smem (72.5 KB).
// out[b,n,o] = gelu(A[n,:62] @ Wf[:,o] + bias).  f32x2 over OUTPUT pairs.
// warp w: nh = w&1 (128-n half), oh = w>>1 (16-output half).
// lane l: 4 n (nl = 128*nh + 4*l), 16 outputs -> acc[4][8] u64 (64 regs).
// Per r per warp: 1 LDS.128 (A) + 4 uniform LDS.128 (W) -> 32 FFMA2.
__global__ void __launch_bounds__(128, 3) k_out(const float* __restrict__ xext,
                                                float* __restrict__ oext, int d) {
    const float* xin = (d == 0) ? xext : g_buf;
    float* out       = (d == 3) ? oext : g_buf;
    int tile = blockIdx.x, b = blockIdx.y;
    int t = threadIdx.x;
    int n0 = tile << 8;                                   // 256-n tile

    extern __shared__ float smem_dyn[];
    float* As = smem_dyn;                                 // [62][PITCH2]
    u64*   Wu = (u64*)(smem_dyn + 62 * PITCH2);           // [62*16]
    float* bs = smem_dyn + 62 * PITCH2 + 62 * 16 * 2;     // [32]

    // trig rows 0..29 (256 cols, two 128-col halves per thread)
#pragma unroll
    for (int r = 0; r < 15; r++) {
        As[r * PITCH2 + t]       = g_twC[(r + 1) * N_ + n0 + t];
        As[r * PITCH2 + t + 128] = g_twC[(r + 1) * N_ + n0 + t + 128];
    }
#pragma unroll
    for (int r = 15; r < 30; r++) {
        As[r * PITCH2 + t]       = g_twS[(r - 14) * N_ + n0 + t];
        As[r * PITCH2 + t + 128] = g_twS[(r - 14) * N_ + n0 + t + 128];
    }
    // x rows 30..61 (transposed): 256 n x 32 c
    const float4* x4 = (const float4*)(xin + ((size_t)b << 19));
#pragma unroll
    for (int k = 0; k < 16; k++) {
        int lin = k * 128 + t;
        int cq = lin & 7, nl = lin >> 3;
        float4 v = x4[(size_t)(n0 + nl) * 8 + cq];
        As[(30 + 4 * cq) * PITCH2 + nl] = v.x;
        As[(31 + 4 * cq) * PITCH2 + nl] = v.y;
        As[(32 + 4 * cq) * PITCH2 + nl] = v.z;
        As[(33 + 4 * cq) * PITCH2 + nl] = v.w;
    }
    const u64* Wb8 = (const u64*)(g_W + (size_t)b * 62 * C_);
    for (int lin = t; lin < 62 * 16; lin += 128) Wu[lin] = Wb8[lin];
    if (t < 32) bs[t] = g_bias[b * C_ + t];
    __syncthreads();

    int w = t >> 5, l = t & 31;
    int nh = w & 1, oh = w >> 1;
    int nl = 128 * nh + 4 * l;
    int o0 = oh * 16;

    u64 acc[4][8];
#pragma unroll
    for (int i = 0; i < 4; i++)
#pragma unroll
        for (int k = 0; k < 8; k++) acc[i][k] = 0ull;

    const float* ap = As + nl;
    const ulonglong2* wpv = (const ulonglong2*)Wu + oh * 4;   // per r: +8
#pragma unroll 2
    for (int r = 0; r < 62; r++) {
        float4 av = *(const float4*)(ap + r * PITCH2);
        ulonglong2 w0 = wpv[r * 8 + 0];
        ulonglong2 w1 = wpv[r * 8 + 1];
        ulonglong2 w2 = wpv[r * 8 + 2];
        ulonglong2 w3 = wpv[r * 8 + 3];
        u64 ws[8] = {w0.x, w0.y, w1.x, w1.y, w2.x, w2.y, w3.x, w3.y};
        u64 a0 = pk2(av.x, av.x);
        u64 a1 = pk2(av.y, av.y);
        u64 a2 = pk2(av.z, av.z);
        u64 a3 = pk2(av.w, av.w);
#pragma unroll
        for (int k = 0; k < 8; k++) {
            acc[0][k] = f2fma(a0, ws[k], acc[0][k]);
            acc[1][k] = f2fma(a1, ws[k], acc[1][k]);
            acc[2][k] = f2fma(a2, ws[k], acc[2][k]);
            acc[3][k] = f2fma(a3, ws[k], acc[3][k]);
        }
    }

    // epilogue: bias + gelu + store (each thread: 4 n x 16 channels)
#pragma unroll
    for (int nn = 0; nn < 4; nn++) {
        float res[16];
#pragma unroll
        for (int k = 0; k < 8; k++) {
            float2 f = upk(acc[nn][k]);
            res[2 * k]     = gelu_f(f.x + bs[o0 + 2 * k]);
            res[2 * k + 1] = gelu_f(f.y + bs[o0 + 2 * k + 1]);
        }
        float* op = out + (((size_t)b << 14) + n0 + nl + nn) * C_ + o0;
#pragma unroll
        for (int j = 0; j < 4; j++)
            *(float4*)(op + 4 * j) =
                make_float4(res[4 * j], res[4 * j + 1], res[4 * j + 2], res[4 * j + 3]);
    }
}

// ------------------------------- launch ------------------------------------
extern "C" void kernel_launch(void* const* d_in, const int* in_sizes, int n_in,
                              void* d_out, int out_size) {
    const float* x  = (const float*)d_in[0];
    const float* Wr = (const float*)d_in[1];
    const float* Wi = (const float*)d_in[2];
    const float* ck = (const float*)d_in[3];
    const float* cb = (const float*)d_in[4];
    float* out = (float*)d_out;

    cudaFuncSetAttribute(k_out, cudaFuncAttributeMaxDynamicSharedMemorySize, KOUT_SMEM);

    k_init<<<(MODES * N_) / 256, 256>>>();
    for (int d = 0; d < 4; d++) {
        k_dft<<<dim3(NSPLIT, B_), 256>>>(x, d);
        k_mix<<<B_, 512>>>(Wr, Wi, ck, cb, d);
        k_out<<<dim3(N_ / 256, B_), 128, KOUT_SMEM>>>(x, out, d);
    }
}